// round 7
// baseline (speedup 1.0000x reference)
#include <cuda_runtime.h>
#include <math.h>

#define DIMX 1024
#define NH   16
#define HD   64
#define DFF  4096
#define BB   2
#define SSQ  2048
#define MTOT (BB*SSQ)
#define QKVN 3072
#define EPSV 1e-6f

// ---------------- scratch (device globals) ----------------------------------
__device__ __align__(256) float g_h   [MTOT*DIMX];
__device__ __align__(256) float g_qkv [MTOT*QKVN];
__device__ __align__(256) float g_attn[MTOT*DIMX];
__device__ __align__(256) float g_x2  [MTOT*DIMX];
__device__ __align__(256) float g_ffh [MTOT*DFF];
__device__ __align__(256) float g_wt  [12*1024*1024];  // transposed tf32 weights

// ---------------- helpers ----------------------------------------------------
__device__ __forceinline__ unsigned f2tf(float f) {
    unsigned u;
    asm("cvt.rna.tf32.f32 %0, %1;" : "=r"(u) : "f"(f));
    return u;
}
__device__ __forceinline__ void cp16(unsigned s, const void* g) {
    asm volatile("cp.async.cg.shared.global [%0], [%1], 16;" :: "r"(s), "l"(g));
}
#define CP_COMMIT() asm volatile("cp.async.commit_group;")
#define CP_WAIT(n)  asm volatile("cp.async.wait_group %0;" :: "n"(n))

#define MMA_TF32(c, a0, a1, a2, a3, b0, b1) asm volatile( \
    "mma.sync.aligned.m16n8k8.row.col.f32.tf32.tf32.f32 " \
    "{%0,%1,%2,%3}, {%4,%5,%6,%7}, {%8,%9}, {%0,%1,%2,%3};" \
    : "+f"((c)[0]), "+f"((c)[1]), "+f"((c)[2]), "+f"((c)[3]) \
    : "r"(a0), "r"(a1), "r"(a2), "r"(a3), "r"(b0), "r"(b1))

#define LDSM4(r, a) asm volatile( \
    "ldmatrix.sync.aligned.m8n8.x4.shared.b16 {%0,%1,%2,%3}, [%4];" \
    : "=r"((r)[0]), "=r"((r)[1]), "=r"((r)[2]), "=r"((r)[3]) : "r"(a))

// ---------------- weight prep: transpose [K,N]->[N,K] + tf32 round ------------
__global__ void __launch_bounds__(256) prep_w(const float* __restrict__ w,
                                              float* __restrict__ o, int K, int N)
{
    __shared__ float t[32][33];
    int kt = blockIdx.y << 5, nb = blockIdx.x << 5;
    int tid = threadIdx.x;
    #pragma unroll
    for (int i = 0; i < 4; i++) {
        int idx = tid + (i << 8);
        int r = idx >> 5, c = idx & 31;
        t[r][c] = w[(size_t)(kt + r) * N + nb + c];
    }
    __syncthreads();
    #pragma unroll
    for (int i = 0; i < 4; i++) {
        int idx = tid + (i << 8);
        int r = idx >> 5, c = idx & 31;     // r = n-local, c = k-local
        reinterpret_cast<unsigned*>(o)[(size_t)(nb + r) * K + kt + c] = f2tf(t[c][r]);
    }
}

// ---------------- LayerNorm (emits tf32-rounded) ------------------------------
__global__ void __launch_bounds__(256) ln_kernel(
    const float* __restrict__ x, const float* __restrict__ alpha,
    const float* __restrict__ beta, float* __restrict__ y)
{
    int row = blockIdx.x;
    int t = threadIdx.x;
    const float4* xr = reinterpret_cast<const float4*>(x + (size_t)row * DIMX);
    float4 v = xr[t];
    float s  = v.x + v.y + v.z + v.w;
    float sq = v.x*v.x + v.y*v.y + v.z*v.z + v.w*v.w;
    #pragma unroll
    for (int o = 16; o; o >>= 1) {
        s  += __shfl_xor_sync(0xffffffffu, s,  o);
        sq += __shfl_xor_sync(0xffffffffu, sq, o);
    }
    __shared__ float ss[8], ssq[8];
    int w = t >> 5, l = t & 31;
    if (l == 0) { ss[w] = s; ssq[w] = sq; }
    __syncthreads();
    if (w == 0) {
        s  = (l < 8) ? ss[l]  : 0.f;
        sq = (l < 8) ? ssq[l] : 0.f;
        #pragma unroll
        for (int o = 4; o; o >>= 1) {
            s  += __shfl_xor_sync(0xffffffffu, s,  o);
            sq += __shfl_xor_sync(0xffffffffu, sq, o);
        }
        if (l == 0) { ss[0] = s; ssq[0] = sq; }
    }
    __syncthreads();
    s = ss[0]; sq = ssq[0];
    float mu  = s * (1.0f / DIMX);
    float var = (sq - (float)DIMX * mu * mu) * (1.0f / (DIMX - 1));
    float sig = sqrtf(fmaxf(var, 0.f));
    float inv = 1.0f / (sig + EPSV);
    float4 a = reinterpret_cast<const float4*>(alpha)[t];
    float4 b = reinterpret_cast<const float4*>(beta)[t];
    uint4 o4;
    o4.x = f2tf(a.x * (v.x - mu) * inv + b.x);
    o4.y = f2tf(a.y * (v.y - mu) * inv + b.y);
    o4.z = f2tf(a.z * (v.z - mu) * inv + b.z);
    o4.w = f2tf(a.w * (v.w - mu) * inv + b.w);
    reinterpret_cast<uint4*>(y + (size_t)row * DIMX)[t] = o4;
}

// ---------------- TF32 tensor GEMM: 128x256 tile, 64x64 warp tiles -------------
// C[M,N] = A[M,K] @ Bt[N,K]^T. 3 smem stages, ldmatrix frags, 8 warps (2m x 4n).
#define SROW 36
#define A_U32 (128*SROW)
#define B_U32 (256*SROW)
#define STAGE_U32 (A_U32 + B_U32)
#define GEMM_SMEM (3 * STAGE_U32 * 4)

template<int OM, bool BIAS, bool RELU, bool RES>
__global__ void __launch_bounds__(256, 1) gemm_tc(
    const float* __restrict__ A, const float* __restrict__ Bt,
    const float* __restrict__ bias, const float* __restrict__ res,
    float* __restrict__ C, int M, int N, int K)
{
    extern __shared__ unsigned smg[];
    const int tid  = threadIdx.x;
    const int bm   = blockIdx.y * 128, bn = blockIdx.x * 256;
    const int warp = tid >> 5, lane = tid & 31;
    const int wm   = (warp >> 2) << 6;       // 0 or 64
    const int wn   = (warp & 3) << 6;        // 0,64,128,192
    const int g    = lane >> 2, q = lane & 3;
    const int lr   = (lane & 7) + ((lane >> 3) & 1) * 8;
    const int lc   = (lane >> 4) * 4;

    const int arow = tid >> 3;               // 0..31 (x4 passes)
    const int brow = tid >> 3;               // 0..31 (x8 passes)
    const int ldc  = (tid & 7) << 2;
    const unsigned sbase = (unsigned)__cvta_generic_to_shared(smg);

    float acc[4][8][4];
    #pragma unroll
    for (int mi = 0; mi < 4; mi++)
        #pragma unroll
        for (int nj = 0; nj < 8; nj++)
            #pragma unroll
            for (int e = 0; e < 4; e++) acc[mi][nj][e] = 0.f;

    const int nt = K >> 5;

    #define G_ISSUE(buf, kt) do { \
        unsigned ab_ = sbase + (buf) * (STAGE_U32 * 4); \
        unsigned bb_ = ab_ + A_U32 * 4; \
        _Pragma("unroll") \
        for (int i_ = 0; i_ < 4; i_++) { \
            int row_ = arow + (i_ << 5); \
            cp16(ab_ + (row_ * SROW + ldc) * 4, A  + (size_t)(bm + row_) * K + (kt) * 32 + ldc); \
        } \
        _Pragma("unroll") \
        for (int i_ = 0; i_ < 8; i_++) { \
            int row_ = brow + (i_ << 5); \
            cp16(bb_ + (row_ * SROW + ldc) * 4, Bt + (size_t)(bn + row_) * K + (kt) * 32 + ldc); \
        } \
    } while (0)

    G_ISSUE(0, 0); CP_COMMIT();
    G_ISSUE(1, 1); CP_COMMIT();

    for (int kt = 0; kt < nt; kt++) {
        CP_WAIT(1);
        __syncthreads();
        int nl = kt + 2;
        if (nl < nt) G_ISSUE(nl % 3, nl);
        CP_COMMIT();

        const unsigned ab = sbase + (kt % 3) * (STAGE_U32 * 4);
        const unsigned bb = ab + A_U32 * 4;
        #pragma unroll
        for (int ks = 0; ks < 4; ks++) {
            const int kk = ks << 3;
            unsigned af[4][4], bp[4][4];
            #pragma unroll
            for (int mi = 0; mi < 4; mi++) {
                unsigned ad = ab + (((wm + (mi << 4) + lr) * SROW) + kk + lc) * 4;
                LDSM4(af[mi], ad);
            }
            #pragma unroll
            for (int p = 0; p < 4; p++) {
                unsigned bd = bb + (((wn + (p << 4) + lr) * SROW) + kk + lc) * 4;
                LDSM4(bp[p], bd);
            }
            #pragma unroll
            for (int mi = 0; mi < 4; mi++)
                #pragma unroll
                for (int nj = 0; nj < 8; nj++)
                    MMA_TF32(acc[mi][nj],
                             af[mi][0], af[mi][1], af[mi][2], af[mi][3],
                             bp[nj >> 1][nj & 1], bp[nj >> 1][2 + (nj & 1)]);
        }
    }

    // epilogue
    #pragma unroll
    for (int mi = 0; mi < 4; mi++) {
        int r = bm + wm + (mi << 4) + g;
        #pragma unroll
        for (int nj = 0; nj < 8; nj++) {
            int c = bn + wn + (nj << 3) + (q << 1);
            float2 v0, v1;
            v0.x = acc[mi][nj][0]; v0.y = acc[mi][nj][1];
            v1.x = acc[mi][nj][2]; v1.y = acc[mi][nj][3];
            if (BIAS) {
                float2 bv = *reinterpret_cast<const float2*>(bias + c);
                v0.x += bv.x; v0.y += bv.y; v1.x += bv.x; v1.y += bv.y;
            }
            if (RELU) {
                v0.x = fmaxf(v0.x, 0.f); v0.y = fmaxf(v0.y, 0.f);
                v1.x = fmaxf(v1.x, 0.f); v1.y = fmaxf(v1.y, 0.f);
            }
            if (RES) {
                float2 r0 = *reinterpret_cast<const float2*>(res + (size_t)r * N + c);
                float2 r1 = *reinterpret_cast<const float2*>(res + (size_t)(r + 8) * N + c);
                v0.x += r0.x; v0.y += r0.y; v1.x += r1.x; v1.y += r1.y;
            }
            if (OM == 1) {
                v0.x = __uint_as_float(f2tf(v0.x)); v0.y = __uint_as_float(f2tf(v0.y));
                v1.x = __uint_as_float(f2tf(v1.x)); v1.y = __uint_as_float(f2tf(v1.y));
            }
            *reinterpret_cast<float2*>(C + (size_t)r * N + c) = v0;
            *reinterpret_cast<float2*>(C + (size_t)(r + 8) * N + c) = v1;
        }
    }
}

// ---------------- TF32 flash attention (unchanged from round 6) ---------------
#define AQS 68
#define AKS 68
#define AVS 72
#define APS 68
#define ATT_SMEM ((128*AQS + 2*64*AKS + 2*64*AVS) * 4)

__global__ void __launch_bounds__(256, 2) attn_tc(
    const float* __restrict__ qkv, float* __restrict__ og)
{
    extern __shared__ unsigned sma[];
    unsigned* Vs = sma + 128 * AQS + 2 * 64 * AKS;
    unsigned* Ps = sma;                   // aliases Qs

    const int tid  = threadIdx.x;
    const int warp = tid >> 5, lane = tid & 31;
    const int g    = lane >> 2, q4 = lane & 3;
    const int lr   = (lane & 7) + ((lane >> 3) & 1) * 8;
    const int lc   = (lane >> 4) * 4;
    const int bh   = blockIdx.y;
    const int b    = bh >> 4, h = bh & 15;
    const int q0   = blockIdx.x * 128;
    const int r0   = warp << 4;
    const size_t rbase = (size_t)b * SSQ;
    const float* qg = qkv + h * HD;
    const float* kg = qkv + DIMX + h * HD;
    const float* vg = qkv + 2 * DIMX + h * HD;

    const unsigned sbase = (unsigned)__cvta_generic_to_shared(sma);
    const unsigned ksb = sbase + 128 * AQS * 4;
    const unsigned vsb = ksb + 2 * 64 * AKS * 4;

    #pragma unroll
    for (int i = 0; i < 8; i++) {
        int f = tid + (i << 8);
        int row = f >> 4;
        int d4 = (f & 15) << 2;
        cp16(sbase + (row * AQS + d4) * 4, qg + (rbase + q0 + row) * QKVN + d4);
    }
    CP_COMMIT();

    #define A_ISSUE(buf, kt) do { \
        _Pragma("unroll") \
        for (int i_ = 0; i_ < 4; i_++) { \
            int f_ = tid + (i_ << 8); \
            int key_ = f_ >> 4; \
            int d4_ = (f_ & 15) << 2; \
            size_t go_ = (rbase + (kt) + key_) * QKVN + d4_; \
            cp16(ksb + ((buf) * 64 * AKS + key_ * AKS + d4_) * 4, kg + go_); \
            cp16(vsb + ((buf) * 64 * AVS + key_ * AVS + d4_) * 4, vg + go_); \
        } \
    } while (0)

    CP_WAIT(0);
    __syncthreads();
    unsigned aq[8][4];
    #pragma unroll
    for (int ks = 0; ks < 8; ks++) {
        unsigned ad = sbase + (((r0 + lr) * AQS) + (ks << 3) + lc) * 4;
        LDSM4(aq[ks], ad);
    }

    A_ISSUE(0, 0);
    CP_COMMIT();

    float m0 = -1e30f, m1 = -1e30f, l0 = 0.f, l1 = 0.f;
    float oacc[8][4];
    #pragma unroll
    for (int j = 0; j < 8; j++)
        #pragma unroll
        for (int e = 0; e < 4; e++) oacc[j][e] = 0.f;

    const int NKT = SSQ / 64;
    for (int t = 0; t < NKT; t++) {
        __syncthreads();
        if (t + 1 < NKT) A_ISSUE((t + 1) & 1, (t + 1) * 64);
        CP_COMMIT();
        CP_WAIT(1);
        __syncthreads();

        const unsigned kbb = ksb + (t & 1) * 64 * AKS * 4;
        const unsigned* Vb = Vs + (t & 1) * 64 * AVS;

        float s[8][4];
        #pragma unroll
        for (int j = 0; j < 8; j++)
            #pragma unroll
            for (int e = 0; e < 4; e++) s[j][e] = 0.f;
        #pragma unroll
        for (int ks = 0; ks < 8; ks++) {
            const int kk = ks << 3;
            unsigned bk[4][4];
            #pragma unroll
            for (int p = 0; p < 4; p++) {
                unsigned bd = kbb + ((((p << 4) + lr) * AKS) + kk + lc) * 4;
                LDSM4(bk[p], bd);
            }
            #pragma unroll
            for (int j = 0; j < 8; j++)
                MMA_TF32(s[j], aq[ks][0], aq[ks][1], aq[ks][2], aq[ks][3],
                         bk[j >> 1][j & 1], bk[j >> 1][2 + (j & 1)]);
        }

        float mt0 = -1e30f, mt1 = -1e30f;
        #pragma unroll
        for (int j = 0; j < 8; j++) {
            s[j][0] *= 0.125f; s[j][1] *= 0.125f; s[j][2] *= 0.125f; s[j][3] *= 0.125f;
            mt0 = fmaxf(mt0, fmaxf(s[j][0], s[j][1]));
            mt1 = fmaxf(mt1, fmaxf(s[j][2], s[j][3]));
        }
        mt0 = fmaxf(mt0, __shfl_xor_sync(0xffffffffu, mt0, 1));
        mt0 = fmaxf(mt0, __shfl_xor_sync(0xffffffffu, mt0, 2));
        mt1 = fmaxf(mt1, __shfl_xor_sync(0xffffffffu, mt1, 1));
        mt1 = fmaxf(mt1, __shfl_xor_sync(0xffffffffu, mt1, 2));
        float mn0 = fmaxf(m0, mt0), mn1 = fmaxf(m1, mt1);
        float corr0 = __expf(m0 - mn0), corr1 = __expf(m1 - mn1);
        m0 = mn0; m1 = mn1;
        float ls0 = 0.f, ls1 = 0.f;
        #pragma unroll
        for (int j = 0; j < 8; j++) {
            float p0 = __expf(s[j][0] - mn0);
            float p1 = __expf(s[j][1] - mn0);
            float p2 = __expf(s[j][2] - mn1);
            float p3 = __expf(s[j][3] - mn1);
            ls0 += p0 + p1; ls1 += p2 + p3;
            uint2 u0; u0.x = f2tf(p0); u0.y = f2tf(p1);
            uint2 u1; u1.x = f2tf(p2); u1.y = f2tf(p3);
            *reinterpret_cast<uint2*>(Ps + (r0 + g) * APS + (j << 3) + (q4 << 1)) = u0;
            *reinterpret_cast<uint2*>(Ps + (r0 + 8 + g) * APS + (j << 3) + (q4 << 1)) = u1;
        }
        ls0 += __shfl_xor_sync(0xffffffffu, ls0, 1);
        ls0 += __shfl_xor_sync(0xffffffffu, ls0, 2);
        ls1 += __shfl_xor_sync(0xffffffffu, ls1, 1);
        ls1 += __shfl_xor_sync(0xffffffffu, ls1, 2);
        l0 = l0 * corr0 + ls0;
        l1 = l1 * corr1 + ls1;
        #pragma unroll
        for (int j = 0; j < 8; j++) {
            oacc[j][0] *= corr0; oacc[j][1] *= corr0;
            oacc[j][2] *= corr1; oacc[j][3] *= corr1;
        }
        __syncwarp();

        #pragma unroll
        for (int ks = 0; ks < 8; ks++) {
            const int kk = ks << 3;
            unsigned ap[4];
            unsigned ad = sbase + (((r0 + lr) * APS) + kk + lc) * 4;
            LDSM4(ap, ad);
            #pragma unroll
            for (int j = 0; j < 8; j++) {
                unsigned b0 = Vb[(kk + q4) * AVS + (j << 3) + g];
                unsigned b1 = Vb[(kk + q4 + 4) * AVS + (j << 3) + g];
                MMA_TF32(oacc[j], ap[0], ap[1], ap[2], ap[3], b0, b1);
            }
        }
    }

    float il0 = 1.0f / l0, il1 = 1.0f / l1;
    #pragma unroll
    for (int j = 0; j < 8; j++) {
        uint2 v0, v1;
        v0.x = f2tf(oacc[j][0] * il0); v0.y = f2tf(oacc[j][1] * il0);
        v1.x = f2tf(oacc[j][2] * il1); v1.y = f2tf(oacc[j][3] * il1);
        size_t o0 = (rbase + q0 + r0 + g) * DIMX + h * HD + (j << 3) + (q4 << 1);
        size_t o1 = (rbase + q0 + r0 + 8 + g) * DIMX + h * HD + (j << 3) + (q4 << 1);
        *reinterpret_cast<uint2*>(og + o0) = v0;
        *reinterpret_cast<uint2*>(og + o1) = v1;
    }
}

// ---------------- launch ------------------------------------------------------
extern "C" void kernel_launch(void* const* d_in, const int* in_sizes, int n_in,
                              void* d_out, int out_size)
{
    const float* x    = (const float*)d_in[0];
    const float* wq   = (const float*)d_in[2];
    const float* wk   = (const float*)d_in[3];
    const float* wv   = (const float*)d_in[4];
    const float* wo   = (const float*)d_in[5];
    const float* w_up = (const float*)d_in[6];
    const float* b_up = (const float*)d_in[7];
    const float* w_dn = (const float*)d_in[8];
    const float* b_dn = (const float*)d_in[9];
    const float* l1a  = (const float*)d_in[10];
    const float* l1b  = (const float*)d_in[11];
    const float* l2a  = (const float*)d_in[12];
    const float* l2b  = (const float*)d_in[13];
    float* out = (float*)d_out;

    float *h, *qkv, *attn, *x2, *ffh, *wt;
    cudaGetSymbolAddress((void**)&h,    g_h);
    cudaGetSymbolAddress((void**)&qkv,  g_qkv);
    cudaGetSymbolAddress((void**)&attn, g_attn);
    cudaGetSymbolAddress((void**)&x2,   g_x2);
    cudaGetSymbolAddress((void**)&ffh,  g_ffh);
    cudaGetSymbolAddress((void**)&wt,   g_wt);

    float* wqkv_t = wt;                        // [3072, 1024]
    float* wo_t   = wt + 3 * 1024 * 1024;      // [1024, 1024]
    float* wu_t   = wt + 4 * 1024 * 1024;      // [4096, 1024]
    float* wd_t   = wt + 8 * 1024 * 1024;      // [1024, 4096]

    cudaFuncSetAttribute(gemm_tc<1,false,false,false>, cudaFuncAttributeMaxDynamicSharedMemorySize, GEMM_SMEM);
    cudaFuncSetAttribute(gemm_tc<0,false,false,true >, cudaFuncAttributeMaxDynamicSharedMemorySize, GEMM_SMEM);
    cudaFuncSetAttribute(gemm_tc<1,true ,true ,false>, cudaFuncAttributeMaxDynamicSharedMemorySize, GEMM_SMEM);
    cudaFuncSetAttribute(gemm_tc<0,true ,false,true >, cudaFuncAttributeMaxDynamicSharedMemorySize, GEMM_SMEM);
    cudaFuncSetAttribute(attn_tc, cudaFuncAttributeMaxDynamicSharedMemorySize, ATT_SMEM);

    dim3 thr(256);

    // launch order puts the QKV GEMM at index 5 so ncu (-s 5 -c 1) captures it
    prep_w<<<dim3(DIMX/32, DIMX/32), thr>>>(wq,   wqkv_t,               DIMX, DIMX);  // 0
    prep_w<<<dim3(DIMX/32, DIMX/32), thr>>>(wk,   wqkv_t + 1024*1024,   DIMX, DIMX);  // 1
    prep_w<<<dim3(DIMX/32, DIMX/32), thr>>>(wv,   wqkv_t + 2*1024*1024, DIMX, DIMX);  // 2
    prep_w<<<dim3(DIMX/32, DIMX/32), thr>>>(wo,   wo_t,                 DIMX, DIMX);  // 3
    ln_kernel<<<MTOT, thr>>>(x, l1a, l1b, h);                                          // 4

    gemm_tc<1,false,false,false><<<dim3(QKVN/256, MTOT/128), thr, GEMM_SMEM>>>(
        h, wqkv_t, nullptr, nullptr, qkv, MTOT, QKVN, DIMX);                           // 5

    attn_tc<<<dim3(SSQ/128, BB*NH), thr, ATT_SMEM>>>(qkv, attn);

    gemm_tc<0,false,false,true><<<dim3(DIMX/256, MTOT/128), thr, GEMM_SMEM>>>(
        attn, wo_t, nullptr, x, x2, MTOT, DIMX, DIMX);

    ln_kernel<<<MTOT, thr>>>(x2, l2a, l2b, h);

    prep_w<<<dim3(DFF/32,  DIMX/32), thr>>>(w_up, wu_t, DIMX, DFF);
    gemm_tc<1,true,true,false><<<dim3(DFF/256, MTOT/128), thr, GEMM_SMEM>>>(
        h, wu_t, b_up, nullptr, ffh, MTOT, DFF, DIMX);

    prep_w<<<dim3(DIMX/32, DFF/32),  thr>>>(w_dn, wd_t, DFF, DIMX);
    gemm_tc<0,true,false,true><<<dim3(DIMX/256, MTOT/128), thr, GEMM_SMEM>>>(
        ffh, wd_t, b_dn, x2, out, MTOT, DIMX, DFF);
}

// round 8
// speedup vs baseline: 1.0841x; 1.0841x over previous
#include <cuda_runtime.h>
#include <math.h>

#define DIMX 1024
#define NH   16
#define HD   64
#define DFF  4096
#define BB   2
#define SSQ  2048
#define MTOT (BB*SSQ)
#define EPSV 1e-6f

// ---------------- scratch (device globals) ----------------------------------
__device__ __align__(256) float g_h   [MTOT*DIMX];
__device__ __align__(256) float g_q   [MTOT*DIMX];
__device__ __align__(256) float g_k   [MTOT*DIMX];
__device__ __align__(256) float g_v   [MTOT*DIMX];
__device__ __align__(256) float g_attn[MTOT*DIMX];
__device__ __align__(256) float g_x2  [MTOT*DIMX];
__device__ __align__(256) float g_ffh [MTOT*DFF];
__device__ __align__(256) float g_wc  [4*DIMX*DIMX + 2*DIMX*DFF];   // tf32 weights

// ---------------- helpers ----------------------------------------------------
__device__ __forceinline__ unsigned f2tf(float f) {
    unsigned u;
    asm("cvt.rna.tf32.f32 %0, %1;" : "=r"(u) : "f"(f));
    return u;
}
__device__ __forceinline__ void cp16(unsigned s, const void* g) {
    asm volatile("cp.async.cg.shared.global [%0], [%1], 16;" :: "r"(s), "l"(g));
}
#define CP_COMMIT() asm volatile("cp.async.commit_group;")
#define CP_WAIT(n)  asm volatile("cp.async.wait_group %0;" :: "n"(n))

#define MMA_TF32(c, a, b) asm volatile( \
    "mma.sync.aligned.m16n8k8.row.col.f32.tf32.tf32.f32 " \
    "{%0,%1,%2,%3}, {%4,%5,%6,%7}, {%8,%9}, {%0,%1,%2,%3};" \
    : "+f"((c)[0]), "+f"((c)[1]), "+f"((c)[2]), "+f"((c)[3]) \
    : "r"((a)[0]), "r"((a)[1]), "r"((a)[2]), "r"((a)[3]), \
      "r"((b)[0]), "r"((b)[1]))

// ---------------- single-launch weight convert (all 6 weights) ----------------
#define W1 (DIMX*DIMX/4)      // float4 count per 1024x1024 weight
#define W2 (DIMX*DFF/4)       // float4 count per 1024x4096 weight
#define WTOT (4*W1 + 2*W2)

__global__ void __launch_bounds__(256) prep_all(
    const float* __restrict__ wq, const float* __restrict__ wk,
    const float* __restrict__ wv, const float* __restrict__ wo,
    const float* __restrict__ wu, const float* __restrict__ wd,
    float* __restrict__ dst)
{
    int i = blockIdx.x * 256 + threadIdx.x;
    if (i >= WTOT) return;
    const float* src;
    int off;
    if      (i < 1*W1) { src = wq; off = i; }
    else if (i < 2*W1) { src = wk; off = i - 1*W1; }
    else if (i < 3*W1) { src = wv; off = i - 2*W1; }
    else if (i < 4*W1) { src = wo; off = i - 3*W1; }
    else if (i < 4*W1 + W2) { src = wu; off = i - 4*W1; }
    else               { src = wd; off = i - 4*W1 - W2; }
    float4 v = reinterpret_cast<const float4*>(src)[off];
    uint4 u;
    u.x = f2tf(v.x); u.y = f2tf(v.y); u.z = f2tf(v.z); u.w = f2tf(v.w);
    reinterpret_cast<uint4*>(dst)[i] = u;
}

// ---------------- LayerNorm (emits tf32-rounded output) -----------------------
__global__ void __launch_bounds__(256) ln_kernel(
    const float* __restrict__ x, const float* __restrict__ alpha,
    const float* __restrict__ beta, float* __restrict__ y)
{
    int row = blockIdx.x;
    int t = threadIdx.x;
    const float4* xr = reinterpret_cast<const float4*>(x + (size_t)row * DIMX);
    float4 v = xr[t];
    float s  = v.x + v.y + v.z + v.w;
    float sq = v.x*v.x + v.y*v.y + v.z*v.z + v.w*v.w;
    #pragma unroll
    for (int o = 16; o; o >>= 1) {
        s  += __shfl_xor_sync(0xffffffffu, s,  o);
        sq += __shfl_xor_sync(0xffffffffu, sq, o);
    }
    __shared__ float ss[8], ssq[8];
    int w = t >> 5, l = t & 31;
    if (l == 0) { ss[w] = s; ssq[w] = sq; }
    __syncthreads();
    if (w == 0) {
        s  = (l < 8) ? ss[l]  : 0.f;
        sq = (l < 8) ? ssq[l] : 0.f;
        #pragma unroll
        for (int o = 4; o; o >>= 1) {
            s  += __shfl_xor_sync(0xffffffffu, s,  o);
            sq += __shfl_xor_sync(0xffffffffu, sq, o);
        }
        if (l == 0) { ss[0] = s; ssq[0] = sq; }
    }
    __syncthreads();
    s = ss[0]; sq = ssq[0];
    float mu  = s * (1.0f / DIMX);
    float var = (sq - (float)DIMX * mu * mu) * (1.0f / (DIMX - 1));
    float sig = sqrtf(fmaxf(var, 0.f));
    float inv = 1.0f / (sig + EPSV);
    float4 a = reinterpret_cast<const float4*>(alpha)[t];
    float4 b = reinterpret_cast<const float4*>(beta)[t];
    uint4 o4;
    o4.x = f2tf(a.x * (v.x - mu) * inv + b.x);
    o4.y = f2tf(a.y * (v.y - mu) * inv + b.y);
    o4.z = f2tf(a.z * (v.z - mu) * inv + b.z);
    o4.w = f2tf(a.w * (v.w - mu) * inv + b.w);
    reinterpret_cast<uint4*>(y + (size_t)row * DIMX)[t] = o4;
}

// ---------------- TF32 tensor-core GEMM, cp.async 3-stage (round-3 config) ----
#define STAGES 3
#define GPA 36
#define GPB 136
#define STAGE_U32 (128*GPA + 32*GPB)
#define GEMM_SMEM (STAGES * STAGE_U32 * 4)

template<bool BIAS, bool RELU, bool RES, bool CVTOUT>
__global__ void __launch_bounds__(256, 2) gemm_tc(
    const float* __restrict__ A, const float* __restrict__ B,
    const float* __restrict__ bias, const float* __restrict__ res,
    float* __restrict__ C, int M, int N, int K)
{
    extern __shared__ unsigned smg[];
    const int tid  = threadIdx.x;
    const int bm   = blockIdx.y * 128, bn = blockIdx.x * 128;
    const int warp = tid >> 5, lane = tid & 31;
    const int wm   = (warp >> 2) << 6;
    const int wn   = (warp & 3) << 5;
    const int g    = lane >> 2, q = lane & 3;

    const int arow = tid >> 3, acol = (tid & 7) << 2;
    const int brow = tid >> 5, bcol = (tid & 31) << 2;

    const float* Ag = A + (size_t)(bm + arow) * K + acol;
    const float* Bg = B + (size_t)brow * N + bn + bcol;
    const unsigned sbase = (unsigned)__cvta_generic_to_shared(smg);

    float acc[4][4][4];
    #pragma unroll
    for (int mi = 0; mi < 4; mi++)
        #pragma unroll
        for (int nj = 0; nj < 4; nj++)
            #pragma unroll
            for (int e = 0; e < 4; e++) acc[mi][nj][e] = 0.f;

    const int nt = K >> 5;

    #define G_ISSUE(buf, kt) do { \
        unsigned ab_ = sbase + (buf) * (STAGE_U32 * 4); \
        unsigned bb_ = ab_ + 128 * GPA * 4; \
        const float* Ap_ = Ag + (kt) * 32; \
        const float* Bp_ = Bg + (size_t)(kt) * 32 * N; \
        _Pragma("unroll") \
        for (int i_ = 0; i_ < 4; i_++) { \
            cp16(ab_ + ((arow + 32 * i_) * GPA + acol) * 4, Ap_ + (size_t)(32 * i_) * K); \
            cp16(bb_ + ((brow + 8 * i_) * GPB + bcol) * 4, Bp_ + (size_t)(8 * i_) * N); \
        } \
    } while (0)

    #pragma unroll
    for (int s = 0; s < STAGES - 1; s++) {
        if (s < nt) G_ISSUE(s, s);
        CP_COMMIT();
    }

    for (int kt = 0; kt < nt; kt++) {
        CP_WAIT(STAGES - 2);
        __syncthreads();
        int nl = kt + STAGES - 1;
        if (nl < nt) {
            int buf = nl % STAGES;
            G_ISSUE(buf, nl);
        }
        CP_COMMIT();

        const unsigned* Ab = smg + (kt % STAGES) * STAGE_U32;
        const unsigned* Bb = Ab + 128 * GPA;
        #pragma unroll
        for (int ks = 0; ks < 4; ks++) {
            const int kk = ks << 3;
            unsigned af[4][4], bf[4][2];
            #pragma unroll
            for (int mi = 0; mi < 4; mi++) {
                int r = wm + (mi << 4) + g;
                af[mi][0] = Ab[r * GPA + kk + q];
                af[mi][1] = Ab[(r + 8) * GPA + kk + q];
                af[mi][2] = Ab[r * GPA + kk + q + 4];
                af[mi][3] = Ab[(r + 8) * GPA + kk + q + 4];
            }
            #pragma unroll
            for (int nj = 0; nj < 4; nj++) {
                int c = wn + (nj << 3) + g;
                bf[nj][0] = Bb[(kk + q) * GPB + c];
                bf[nj][1] = Bb[(kk + q + 4) * GPB + c];
            }
            #pragma unroll
            for (int mi = 0; mi < 4; mi++)
                #pragma unroll
                for (int nj = 0; nj < 4; nj++)
                    MMA_TF32(acc[mi][nj], af[mi], bf[nj]);
        }
    }

    // epilogue
    #pragma unroll
    for (int mi = 0; mi < 4; mi++) {
        int r = bm + wm + (mi << 4) + g;
        #pragma unroll
        for (int nj = 0; nj < 4; nj++) {
            int c = bn + wn + (nj << 3) + (q << 1);
            float2 v0, v1;
            v0.x = acc[mi][nj][0]; v0.y = acc[mi][nj][1];
            v1.x = acc[mi][nj][2]; v1.y = acc[mi][nj][3];
            if (BIAS) {
                float2 bv = *reinterpret_cast<const float2*>(bias + c);
                v0.x += bv.x; v0.y += bv.y; v1.x += bv.x; v1.y += bv.y;
            }
            if (RELU) {
                v0.x = fmaxf(v0.x, 0.f); v0.y = fmaxf(v0.y, 0.f);
                v1.x = fmaxf(v1.x, 0.f); v1.y = fmaxf(v1.y, 0.f);
            }
            if (RES) {
                float2 r0 = *reinterpret_cast<const float2*>(res + (size_t)r * N + c);
                float2 r1 = *reinterpret_cast<const float2*>(res + (size_t)(r + 8) * N + c);
                v0.x += r0.x; v0.y += r0.y; v1.x += r1.x; v1.y += r1.y;
            }
            if (CVTOUT) {
                v0.x = __uint_as_float(f2tf(v0.x)); v0.y = __uint_as_float(f2tf(v0.y));
                v1.x = __uint_as_float(f2tf(v1.x)); v1.y = __uint_as_float(f2tf(v1.y));
            }
            *reinterpret_cast<float2*>(C + (size_t)r * N + c) = v0;
            *reinterpret_cast<float2*>(C + (size_t)(r + 8) * N + c) = v1;
        }
    }
}

// ---------------- TF32 flash attention (round-3 config) -----------------------
#define AQS 68
#define AKS 68
#define AVS 72
#define APS 68
#define ATT_SMEM ((128*AQS + 2*64*AKS + 2*64*AVS) * 4)

__global__ void __launch_bounds__(256, 2) attn_tc(
    const float* __restrict__ qg, const float* __restrict__ kg,
    const float* __restrict__ vg, float* __restrict__ og)
{
    extern __shared__ unsigned sma[];
    unsigned* Qs = sma;
    unsigned* Ks = Qs + 128 * AQS;
    unsigned* Vs = Ks + 2 * 64 * AKS;
    unsigned* Ps = Qs;                    // alias

    const int tid  = threadIdx.x;
    const int warp = tid >> 5, lane = tid & 31;
    const int g    = lane >> 2, q4 = lane & 3;
    const int bh   = blockIdx.y;
    const int b    = bh >> 4, h = bh & 15;
    const int q0   = blockIdx.x * 128;
    const size_t base = ((size_t)b * SSQ) * DIMX + h * HD;
    const int r0 = warp << 4;
    const unsigned sbase = (unsigned)__cvta_generic_to_shared(sma);
    const unsigned ksb = sbase + 128 * AQS * 4;
    const unsigned vsb = ksb + 2 * 64 * AKS * 4;

    #pragma unroll
    for (int i = 0; i < 8; i++) {
        int f = tid + (i << 8);
        int row = f >> 4;
        int d4 = (f & 15) << 2;
        cp16(sbase + (row * AQS + d4) * 4, qg + base + (size_t)(q0 + row) * DIMX + d4);
    }
    CP_COMMIT();

    #define A_ISSUE(buf, kt) do { \
        _Pragma("unroll") \
        for (int i_ = 0; i_ < 4; i_++) { \
            int f_ = tid + (i_ << 8); \
            int key_ = f_ >> 4; \
            int d4_ = (f_ & 15) << 2; \
            size_t go_ = base + (size_t)((kt) + key_) * DIMX + d4_; \
            cp16(ksb + ((buf) * 64 * AKS + key_ * AKS + d4_) * 4, kg + go_); \
            cp16(vsb + ((buf) * 64 * AVS + key_ * AVS + d4_) * 4, vg + go_); \
        } \
    } while (0)

    CP_WAIT(0);
    __syncthreads();
    unsigned aq[8][4];
    #pragma unroll
    for (int ks = 0; ks < 8; ks++) {
        int kk = ks << 3;
        aq[ks][0] = Qs[(r0 + g) * AQS + kk + q4];
        aq[ks][1] = Qs[(r0 + 8 + g) * AQS + kk + q4];
        aq[ks][2] = Qs[(r0 + g) * AQS + kk + q4 + 4];
        aq[ks][3] = Qs[(r0 + 8 + g) * AQS + kk + q4 + 4];
    }

    A_ISSUE(0, 0);
    CP_COMMIT();

    float m0 = -1e30f, m1 = -1e30f, l0 = 0.f, l1 = 0.f;
    float oacc[8][4];
    #pragma unroll
    for (int j = 0; j < 8; j++)
        #pragma unroll
        for (int e = 0; e < 4; e++) oacc[j][e] = 0.f;

    const int NKT = SSQ / 64;
    for (int t = 0; t < NKT; t++) {
        __syncthreads();
        if (t + 1 < NKT) A_ISSUE((t + 1) & 1, (t + 1) * 64);
        CP_COMMIT();
        CP_WAIT(1);
        __syncthreads();

        const unsigned* Kb = Ks + (t & 1) * 64 * AKS;
        const unsigned* Vb = Vs + (t & 1) * 64 * AVS;

        float s[8][4];
        #pragma unroll
        for (int j = 0; j < 8; j++)
            #pragma unroll
            for (int e = 0; e < 4; e++) s[j][e] = 0.f;
        #pragma unroll
        for (int ks = 0; ks < 8; ks++) {
            int kk = ks << 3;
            #pragma unroll
            for (int j = 0; j < 8; j++) {
                unsigned bfr[2];
                bfr[0] = Kb[((j << 3) + g) * AKS + kk + q4];
                bfr[1] = Kb[((j << 3) + g) * AKS + kk + q4 + 4];
                MMA_TF32(s[j], aq[ks], bfr);
            }
        }

        float mt0 = -1e30f, mt1 = -1e30f;
        #pragma unroll
        for (int j = 0; j < 8; j++) {
            s[j][0] *= 0.125f; s[j][1] *= 0.125f; s[j][2] *= 0.125f; s[j][3] *= 0.125f;
            mt0 = fmaxf(mt0, fmaxf(s[j][0], s[j][1]));
            mt1 = fmaxf(mt1, fmaxf(s[j][2], s[j][3]));
        }
        mt0 = fmaxf(mt0, __shfl_xor_sync(0xffffffffu, mt0, 1));
        mt0 = fmaxf(mt0, __shfl_xor_sync(0xffffffffu, mt0, 2));
        mt1 = fmaxf(mt1, __shfl_xor_sync(0xffffffffu, mt1, 1));
        mt1 = fmaxf(mt1, __shfl_xor_sync(0xffffffffu, mt1, 2));
        float mn0 = fmaxf(m0, mt0), mn1 = fmaxf(m1, mt1);
        float corr0 = __expf(m0 - mn0), corr1 = __expf(m1 - mn1);
        m0 = mn0; m1 = mn1;
        float ls0 = 0.f, ls1 = 0.f;
        #pragma unroll
        for (int j = 0; j < 8; j++) {
            float p0 = __expf(s[j][0] - mn0);
            float p1 = __expf(s[j][1] - mn0);
            float p2 = __expf(s[j][2] - mn1);
            float p3 = __expf(s[j][3] - mn1);
            ls0 += p0 + p1; ls1 += p2 + p3;
            uint2 u0; u0.x = f2tf(p0); u0.y = f2tf(p1);
            uint2 u1; u1.x = f2tf(p2); u1.y = f2tf(p3);
            *reinterpret_cast<uint2*>(Ps + (r0 + g) * APS + (j << 3) + (q4 << 1)) = u0;
            *reinterpret_cast<uint2*>(Ps + (r0 + 8 + g) * APS + (j << 3) + (q4 << 1)) = u1;
        }
        ls0 += __shfl_xor_sync(0xffffffffu, ls0, 1);
        ls0 += __shfl_xor_sync(0xffffffffu, ls0, 2);
        ls1 += __shfl_xor_sync(0xffffffffu, ls1, 1);
        ls1 += __shfl_xor_sync(0xffffffffu, ls1, 2);
        l0 = l0 * corr0 + ls0;
        l1 = l1 * corr1 + ls1;
        #pragma unroll
        for (int j = 0; j < 8; j++) {
            oacc[j][0] *= corr0; oacc[j][1] *= corr0;
            oacc[j][2] *= corr1; oacc[j][3] *= corr1;
        }
        __syncwarp();

        #pragma unroll
        for (int ks = 0; ks < 8; ks++) {
            int kk = ks << 3;
            unsigned ap[4];
            ap[0] = Ps[(r0 + g) * APS + kk + q4];
            ap[1] = Ps[(r0 + 8 + g) * APS + kk + q4];
            ap[2] = Ps[(r0 + g) * APS + kk + q4 + 4];
            ap[3] = Ps[(r0 + 8 + g) * APS + kk + q4 + 4];
            #pragma unroll
            for (int j = 0; j < 8; j++) {
                unsigned bfr[2];
                bfr[0] = Vb[(kk + q4) * AVS + (j << 3) + g];
                bfr[1] = Vb[(kk + q4 + 4) * AVS + (j << 3) + g];
                MMA_TF32(oacc[j], ap, bfr);
            }
        }
    }

    float il0 = 1.0f / l0, il1 = 1.0f / l1;
    #pragma unroll
    for (int j = 0; j < 8; j++) {
        uint2 v0, v1;
        v0.x = f2tf(oacc[j][0] * il0); v0.y = f2tf(oacc[j][1] * il0);
        v1.x = f2tf(oacc[j][2] * il1); v1.y = f2tf(oacc[j][3] * il1);
        size_t o0 = base + (size_t)(q0 + r0 + g) * DIMX + (j << 3) + (q4 << 1);
        size_t o1 = base + (size_t)(q0 + r0 + 8 + g) * DIMX + (j << 3) + (q4 << 1);
        *reinterpret_cast<uint2*>(og + o0) = v0;
        *reinterpret_cast<uint2*>(og + o1) = v1;
    }
}

// ---------------- launch ------------------------------------------------------
extern "C" void kernel_launch(void* const* d_in, const int* in_sizes, int n_in,
                              void* d_out, int out_size)
{
    const float* x    = (const float*)d_in[0];
    const float* wq   = (const float*)d_in[2];
    const float* wk   = (const float*)d_in[3];
    const float* wv   = (const float*)d_in[4];
    const float* wo   = (const float*)d_in[5];
    const float* w_up = (const float*)d_in[6];
    const float* b_up = (const float*)d_in[7];
    const float* w_dn = (const float*)d_in[8];
    const float* b_dn = (const float*)d_in[9];
    const float* l1a  = (const float*)d_in[10];
    const float* l1b  = (const float*)d_in[11];
    const float* l2a  = (const float*)d_in[12];
    const float* l2b  = (const float*)d_in[13];
    float* out = (float*)d_out;

    float *h, *qb, *kb, *vb, *attn, *x2, *ffh, *wc;
    cudaGetSymbolAddress((void**)&h,    g_h);
    cudaGetSymbolAddress((void**)&qb,   g_q);
    cudaGetSymbolAddress((void**)&kb,   g_k);
    cudaGetSymbolAddress((void**)&vb,   g_v);
    cudaGetSymbolAddress((void**)&attn, g_attn);
    cudaGetSymbolAddress((void**)&x2,   g_x2);
    cudaGetSymbolAddress((void**)&ffh,  g_ffh);
    cudaGetSymbolAddress((void**)&wc,   g_wc);

    float* wq_c = wc;
    float* wk_c = wc + 1 * DIMX * DIMX;
    float* wv_c = wc + 2 * DIMX * DIMX;
    float* wo_c = wc + 3 * DIMX * DIMX;
    float* wu_c = wc + 4 * DIMX * DIMX;
    float* wd_c = wu_c + DIMX * DFF;

    cudaFuncSetAttribute(gemm_tc<false,false,false,true >, cudaFuncAttributeMaxDynamicSharedMemorySize, GEMM_SMEM);
    cudaFuncSetAttribute(gemm_tc<false,false,true ,false>, cudaFuncAttributeMaxDynamicSharedMemorySize, GEMM_SMEM);
    cudaFuncSetAttribute(gemm_tc<true ,true ,false,true >, cudaFuncAttributeMaxDynamicSharedMemorySize, GEMM_SMEM);
    cudaFuncSetAttribute(gemm_tc<true ,false,true ,false>, cudaFuncAttributeMaxDynamicSharedMemorySize, GEMM_SMEM);
    cudaFuncSetAttribute(attn_tc, cudaFuncAttributeMaxDynamicSharedMemorySize, ATT_SMEM);

    dim3 thr(256);

    // 0: single weight-convert launch (all 6 weights, tf32 round, no transpose)
    prep_all<<<(WTOT + 255) / 256, thr>>>(wq, wk, wv, wo, w_up, w_dn, wc);

    // 1: h = LN1(x)  (tf32)
    ln_kernel<<<MTOT, thr>>>(x, l1a, l1b, h);

    // 2,3,4: QKV projections (tf32 out)
    gemm_tc<false,false,false,true><<<dim3(DIMX/128, MTOT/128), thr, GEMM_SMEM>>>(h, wq_c, nullptr, nullptr, qb, MTOT, DIMX, DIMX);
    gemm_tc<false,false,false,true><<<dim3(DIMX/128, MTOT/128), thr, GEMM_SMEM>>>(h, wk_c, nullptr, nullptr, kb, MTOT, DIMX, DIMX);
    gemm_tc<false,false,false,true><<<dim3(DIMX/128, MTOT/128), thr, GEMM_SMEM>>>(h, wv_c, nullptr, nullptr, vb, MTOT, DIMX, DIMX);

    // 5: attention (tf32 out)
    attn_tc<<<dim3(SSQ/128, BB*NH), thr, ATT_SMEM>>>(qb, kb, vb, attn);

    // 6: x2 = x + attn @ wo
    gemm_tc<false,false,true,false><<<dim3(DIMX/128, MTOT/128), thr, GEMM_SMEM>>>(attn, wo_c, nullptr, x, x2, MTOT, DIMX, DIMX);

    // 7: h = LN2(x2)
    ln_kernel<<<MTOT, thr>>>(x2, l2a, l2b, h);

    // 8: ffh = relu(h @ w_up + b_up)  (tf32 out)
    gemm_tc<true,true,false,true><<<dim3(DFF/128, MTOT/128), thr, GEMM_SMEM>>>(h, wu_c, b_up, nullptr, ffh, MTOT, DFF, DIMX);

    // 9: out = x2 + ffh @ w_down + b_down
    gemm_tc<true,false,true,false><<<dim3(DIMX/128, MTOT/128), thr, GEMM_SMEM>>>(ffh, wd_c, b_dn, x2, out, MTOT, DIMX, DFF);
}